// round 16
// baseline (speedup 1.0000x reference)
#include <cuda_runtime.h>
#include <cuda_bf16.h>
#include <math.h>
#include <cstdint>

#define D_MODEL 1024
#define D_STATE 16
#define D_CONV  4
#define D_INNER 2048
#define BATCH   2
#define SEQ     1024
#define ROWS    (BATCH * SEQ)          // 2048
#define E2      (2 * D_INNER)          // 4096
#define NXP     128                    // padded x_proj output dim (33 -> 128)
#define KSPLIT_XP 8

// ---------------- scratch (device globals; no allocations) ----------------
__device__ float g_xz[ROWS * E2];          // in_proj output; later: GEMM2 split-K partials
__device__ float g_xconv[ROWS * D_INNER];  // conv+silu output (fp32 for scan)
__device__ float g_xdbl[ROWS * NXP];       // xproj output: B|C|dtraw padded rows
__device__ float g_xpart[KSPLIT_XP * ROWS * NXP];  // xproj split-K partials (8MB)

// bf16 hi/lo split operands for tensor-core GEMMs
__device__ __nv_bfloat16 g_xhi[ROWS * D_MODEL];
__device__ __nv_bfloat16 g_xlo[ROWS * D_MODEL];
__device__ __nv_bfloat16 g_wihi[E2 * D_MODEL];
__device__ __nv_bfloat16 g_wilo[E2 * D_MODEL];
__device__ __nv_bfloat16 g_yyhi[ROWS * D_INNER];
__device__ __nv_bfloat16 g_yylo[ROWS * D_INNER];
__device__ __nv_bfloat16 g_wohi[D_MODEL * D_INNER];
__device__ __nv_bfloat16 g_wolo[D_MODEL * D_INNER];
__device__ __nv_bfloat16 g_xchi[ROWS * D_INNER];   // bf16 hi/lo of conv+silu output
__device__ __nv_bfloat16 g_xclo[ROWS * D_INNER];
// zero-padded x_proj weights (rows 33..127 stay zero)
__device__ __nv_bfloat16 g_xpwhi[NXP * D_INNER];
__device__ __nv_bfloat16 g_xpwlo[NXP * D_INNER];

// ---------------- PTX helpers ---------------------------------------------
__device__ __forceinline__ uint32_t smem_u32(const void* p) {
    uint32_t a;
    asm("{ .reg .u64 t; cvta.to.shared.u64 t, %1; cvt.u32.u64 %0, t; }" : "=r"(a) : "l"(p));
    return a;
}
#define CP_ASYNC16(smem, gmem) \
    asm volatile("cp.async.cg.shared.global [%0], [%1], 16;" :: "r"(smem), "l"(gmem))
#define CP_COMMIT() asm volatile("cp.async.commit_group;" ::: "memory")
#define CP_WAIT2()  asm volatile("cp.async.wait_group 2;" ::: "memory")
#define CP_WAIT1()  asm volatile("cp.async.wait_group 1;" ::: "memory")
#define CP_WAIT0()  asm volatile("cp.async.wait_group 0;" ::: "memory")
#define LDMATRIX_X4(r0, r1, r2, r3, addr) \
    asm volatile("ldmatrix.sync.aligned.m8n8.x4.shared.b16 {%0,%1,%2,%3}, [%4];" \
        : "=r"(r0), "=r"(r1), "=r"(r2), "=r"(r3) : "r"(addr))
#define MMA16816(d, a, b) \
    asm volatile("mma.sync.aligned.m16n8k16.row.col.f32.bf16.bf16.f32 " \
        "{%0,%1,%2,%3}, {%4,%5,%6,%7}, {%8,%9}, {%0,%1,%2,%3};" \
        : "+f"((d)[0]), "+f"((d)[1]), "+f"((d)[2]), "+f"((d)[3]) \
        : "r"((a)[0]), "r"((a)[1]), "r"((a)[2]), "r"((a)[3]), "r"((b)[0]), "r"((b)[1]))

// ---------------- fused split fp32 -> bf16 hi/lo (4 tensors, 1 launch) -----
#define N4_X   (ROWS * D_MODEL / 4)
#define N4_WI  (E2 * D_MODEL / 4)
#define N4_WO  (D_MODEL * D_INNER / 4)
#define N4_XPW (33 * D_INNER / 4)
#define N4_TOT (N4_X + N4_WI + N4_WO + N4_XPW)

__global__ void split_all_kernel(const float* __restrict__ x,
                                 const float* __restrict__ wi,
                                 const float* __restrict__ wo,
                                 const float* __restrict__ xpw) {
    int i = blockIdx.x * blockDim.x + threadIdx.x;
    if (i >= N4_TOT) return;
    const float* in;
    __nv_bfloat16 *hi, *lo;
    int j = i;
    if (j < N4_X)                 { in = x;   hi = g_xhi;   lo = g_xlo; }
    else if ((j -= N4_X) < N4_WI) { in = wi;  hi = g_wihi;  lo = g_wilo; }
    else if ((j -= N4_WI) < N4_WO){ in = wo;  hi = g_wohi;  lo = g_wolo; }
    else { j -= N4_WO;              in = xpw; hi = g_xpwhi; lo = g_xpwlo; }

    float4 v = ((const float4*)in)[j];
    __nv_bfloat16 h0 = __float2bfloat16(v.x);
    __nv_bfloat16 h1 = __float2bfloat16(v.y);
    __nv_bfloat16 h2 = __float2bfloat16(v.z);
    __nv_bfloat16 h3 = __float2bfloat16(v.w);
    ((__nv_bfloat162*)hi)[2 * j]     = __nv_bfloat162(h0, h1);
    ((__nv_bfloat162*)hi)[2 * j + 1] = __nv_bfloat162(h2, h3);
    ((__nv_bfloat162*)lo)[2 * j] =
        __nv_bfloat162(__float2bfloat16(v.x - __bfloat162float(h0)),
                       __float2bfloat16(v.y - __bfloat162float(h1)));
    ((__nv_bfloat162*)lo)[2 * j + 1] =
        __nv_bfloat162(__float2bfloat16(v.z - __bfloat162float(h2)),
                       __float2bfloat16(v.w - __bfloat162float(h3)));
}

// ---------------- HMMA split-bf16 GEMM: C = A @ W^T -----------------------
#define ROW_BYTES   64
#define TILE_SM     (128 * ROW_BYTES)
#define STAGE_SM    (4 * TILE_SM)
#define GEMM_SMEM   (3 * STAGE_SM)

__global__ __launch_bounds__(256, 2) void gemm_hmma_x3(
    const __nv_bfloat16* __restrict__ Ahi, const __nv_bfloat16* __restrict__ Alo,
    const __nv_bfloat16* __restrict__ Whi, const __nv_bfloat16* __restrict__ Wlo,
    float* __restrict__ C, int M, int N, int Kfull, int Ksub) {
    extern __shared__ char dynsmem[];
    const uint32_t sbase = smem_u32(dynsmem);

    const int tid  = threadIdx.x;
    const int warp = tid >> 5;
    const int lane = tid & 31;
    const int rowBase = blockIdx.y * 128;
    const int colBase = blockIdx.x * 128;
    const int kBase   = blockIdx.z * Ksub;
    float* Cz = C + (size_t)blockIdx.z * M * N;

    const int ltile = tid >> 6;
    const int l64   = tid & 63;
    const __nv_bfloat16* lbase =
        (ltile == 0) ? Ahi : (ltile == 1) ? Alo : (ltile == 2) ? Whi : Wlo;
    const int lrbase = (ltile < 2) ? rowBase : colBase;

    const int wrow = (warp & 1) * 64;
    const int wcol = (warp >> 1) * 32;

    float acc[4][4][4];
#pragma unroll
    for (int i = 0; i < 4; i++)
#pragma unroll
        for (int j = 0; j < 4; j++)
#pragma unroll
            for (int r = 0; r < 4; r++) acc[i][j][r] = 0.f;

    const int nk = Ksub >> 5;
    const int lm_row = lane & 15;
    const int lm_ch  = lane >> 4;

    auto issue_stage = [&](int kb) {
        const int k0 = kBase + (kb << 5);
        const uint32_t stg = sbase + (kb % 3) * STAGE_SM + ltile * TILE_SM;
#pragma unroll
        for (int j = 0; j < 8; j++) {
            int idx = l64 + 64 * j;
            int row = idx >> 2;
            int cb  = idx & 3;
            const char* g = (const char*)lbase + ((size_t)(lrbase + row) * Kfull + k0) * 2 + cb * 16;
            uint32_t sc = cb ^ ((row >> 1) & 3);
            CP_ASYNC16(stg + row * ROW_BYTES + sc * 16, g);
        }
    };

    issue_stage(0); CP_COMMIT();
    if (nk > 1) { issue_stage(1); CP_COMMIT(); }

    for (int kb = 0; kb < nk; kb++) {
        const uint32_t stage = sbase + (kb % 3) * STAGE_SM;
        if (kb + 2 < nk) { issue_stage(kb + 2); CP_COMMIT(); CP_WAIT2(); }
        else if (kb + 1 < nk) { CP_WAIT1(); }
        else { CP_WAIT0(); }
        __syncthreads();

#pragma unroll
        for (int k16 = 0; k16 < 2; k16++) {
            const int chunk = k16 * 2 + lm_ch;
            uint32_t aHi[4][4], aLo[4][4], bHi[2][4], bLo[2][4];
#pragma unroll
            for (int mi = 0; mi < 4; mi++) {
                int row = wrow + mi * 16 + lm_row;
                uint32_t sc = (uint32_t)(chunk ^ ((row >> 1) & 3));
                uint32_t addr = stage + 0 * TILE_SM + row * ROW_BYTES + sc * 16;
                LDMATRIX_X4(aHi[mi][0], aHi[mi][1], aHi[mi][2], aHi[mi][3], addr);
                addr += TILE_SM;
                LDMATRIX_X4(aLo[mi][0], aLo[mi][1], aLo[mi][2], aLo[mi][3], addr);
            }
#pragma unroll
            for (int np = 0; np < 2; np++) {
                int row = wcol + np * 16 + lm_row;
                uint32_t sc = (uint32_t)(chunk ^ ((row >> 1) & 3));
                uint32_t addr = stage + 2 * TILE_SM + row * ROW_BYTES + sc * 16;
                LDMATRIX_X4(bHi[np][0], bHi[np][1], bHi[np][2], bHi[np][3], addr);
                addr += TILE_SM;
                LDMATRIX_X4(bLo[np][0], bLo[np][1], bLo[np][2], bLo[np][3], addr);
            }
#pragma unroll
            for (int mi = 0; mi < 4; mi++)
#pragma unroll
                for (int ni = 0; ni < 4; ni++) {
                    const int np = ni >> 1, sub = ni & 1;
                    uint32_t bh[2] = { bHi[np][sub], bHi[np][sub + 2] };
                    uint32_t bl[2] = { bLo[np][sub], bLo[np][sub + 2] };
                    MMA16816(acc[mi][ni], aHi[mi], bh);
                    MMA16816(acc[mi][ni], aLo[mi], bh);
                    MMA16816(acc[mi][ni], aHi[mi], bl);
                }
        }
        __syncthreads();
    }

#pragma unroll
    for (int mi = 0; mi < 4; mi++) {
#pragma unroll
        for (int ni = 0; ni < 4; ni++) {
            int r0 = rowBase + wrow + mi * 16 + (lane >> 2);
            int c0 = colBase + wcol + ni * 8 + (lane & 3) * 2;
            *(float2*)&Cz[(size_t)r0 * N + c0]       = make_float2(acc[mi][ni][0], acc[mi][ni][1]);
            *(float2*)&Cz[(size_t)(r0 + 8) * N + c0] = make_float2(acc[mi][ni][2], acc[mi][ni][3]);
        }
    }
}

// ---------------- split-K reduce: out = p0 + p1 (GEMM2) --------------------
__global__ void addk_kernel(const float* __restrict__ p, float* __restrict__ out, int n4) {
    int i = blockIdx.x * blockDim.x + threadIdx.x;
    if (i >= n4) return;
    float4 a = ((const float4*)p)[i];
    float4 b = ((const float4*)p)[i + n4];
    ((float4*)out)[i] = make_float4(a.x + b.x, a.y + b.y, a.z + b.z, a.w + b.w);
}

// ---------------- xproj split-K reduce: g_xdbl = sum of 8 partials ---------
__global__ void addk8_kernel() {
    int i = blockIdx.x * blockDim.x + threadIdx.x;
    const int n4 = ROWS * NXP / 4;
    if (i >= n4) return;
    float4 s = ((const float4*)g_xpart)[i];
#pragma unroll
    for (int z = 1; z < KSPLIT_XP; z++) {
        float4 v = ((const float4*)g_xpart)[i + (size_t)z * n4];
        s.x += v.x; s.y += v.y; s.z += v.z; s.w += v.w;
    }
    ((float4*)g_xdbl)[i] = s;
}

// ---------------- depthwise causal conv(4) + bias + SiLU (pairs of d) -----
__global__ void conv_silu_kernel(const float* __restrict__ conv_w,
                                 const float* __restrict__ conv_b) {
    int idx = blockIdx.x * blockDim.x + threadIdx.x;     // over ROWS*D_INNER/2
    if (idx >= ROWS * D_INNER / 2) return;
    int d2 = idx & (D_INNER / 2 - 1);
    int d = d2 * 2;
    int row = idx >> 10;
    int l = row & (SEQ - 1);
    int b = row >> 10;

    float a0 = conv_b[d], a1 = conv_b[d + 1];
#pragma unroll
    for (int j = 0; j < D_CONV; j++) {
        int ls = l - (D_CONV - 1) + j;
        if (ls >= 0) {
            float2 xv = *(const float2*)&g_xz[(size_t)(b * SEQ + ls) * E2 + d];
            a0 = fmaf(conv_w[d * D_CONV + j], xv.x, a0);
            a1 = fmaf(conv_w[(d + 1) * D_CONV + j], xv.y, a1);
        }
    }
    float r0 = a0 / (1.f + __expf(-a0));
    float r1 = a1 / (1.f + __expf(-a1));
    size_t o = (size_t)row * D_INNER + d;
    *(float2*)&g_xconv[o] = make_float2(r0, r1);
    __nv_bfloat16 h0 = __float2bfloat16(r0);
    __nv_bfloat16 h1 = __float2bfloat16(r1);
    *(__nv_bfloat162*)&g_xchi[o] = __nv_bfloat162(h0, h1);
    *(__nv_bfloat162*)&g_xclo[o] =
        __nv_bfloat162(__float2bfloat16(r0 - __bfloat162float(h0)),
                       __float2bfloat16(r1 - __bfloat162float(h1)));
}

// ---------------- selective scan: 8 lanes/channel, 4 channels/warp --------
// lane = 8*c + j; lane holds states 2j, 2j+1 of channel c. 1024 warps total.
template<bool FAST>
__device__ __forceinline__ void scan_loop(
    int j, int d, size_t rbase,
    float A0, float A1, float dtwd, float dtbd) {
    const float*  pu = g_xconv + rbase * D_INNER + d;
    const float*  px = g_xdbl + rbase * NXP;
    const float*  pz = g_xz + rbase * E2 + D_INNER + d;

    float u_pf[8], t_pf[8], z_pf[8];
    float2 B_pf[8], C_pf[8];
#pragma unroll
    for (int i = 0; i < 8; i++) {
        u_pf[i] = pu[(size_t)i * D_INNER];
        t_pf[i] = px[i * NXP + 32];
        z_pf[i] = pz[(size_t)i * E2];
        B_pf[i] = *(const float2*)&px[i * NXP + 2 * j];
        C_pf[i] = *(const float2*)&px[i * NXP + 16 + 2 * j];
    }

    float s0 = 0.f, s1 = 0.f;
    const unsigned full = 0xFFFFFFFFu;

#pragma unroll 8
    for (int l = 0; l < SEQ; l++) {
        const int q = l & 7;
        const float u = u_pf[q], traw = t_pf[q], zv = z_pf[q];
        const float2 Bv = B_pf[q], Cv = C_pf[q];
        if (l + 8 < SEQ) {
            const int r = l + 8;
            u_pf[q] = pu[(size_t)r * D_INNER];
            t_pf[q] = px[r * NXP + 32];
            z_pf[q] = pz[(size_t)r * E2];
            B_pf[q] = *(const float2*)&px[r * NXP + 2 * j];
            C_pf[q] = *(const float2*)&px[r * NXP + 16 + 2 * j];
        }
        float v = fmaf(traw, dtwd, dtbd);
        float dt = (v > 20.f) ? v : __logf(1.f + __expf(v));
        float dtu = dt * u;

        float Ab0, Ab1;
        if (FAST) {
            // states 2j+1, 2j+2 (1-indexed exponents of E = exp(-dt))
            float e1 = __expf(-dt);
            float e2 = e1 * e1;
            float e4 = e2 * e2;
            float e8 = e4 * e4;
            float base = ((j & 1) ? e2 : 1.f) * ((j & 2) ? e4 : 1.f) * ((j & 4) ? e8 : 1.f);
            Ab0 = base * e1;
            Ab1 = base * e2;
        } else {
            Ab0 = __expf(dt * A0);
            Ab1 = __expf(dt * A1);
        }

        s0 = fmaf(Ab0, s0, dtu * Bv.x);
        s1 = fmaf(Ab1, s1, dtu * Bv.y);

        float p = s0 * Cv.x;
        p = fmaf(s1, Cv.y, p);
        p += __shfl_xor_sync(full, p, 1);
        p += __shfl_xor_sync(full, p, 2);
        p += __shfl_xor_sync(full, p, 4);

        if (j == 0) {
            float sz = zv / (1.f + __expf(-zv));
            float vv = p * sz;
            __nv_bfloat16 h = __float2bfloat16(vv);
            size_t o = (rbase + l) * D_INNER + d;
            g_yyhi[o] = h;
            g_yylo[o] = __float2bfloat16(vv - __bfloat162float(h));
        }
    }
}

__global__ __launch_bounds__(32) void scan_kernel(const float* __restrict__ A_log,
                                                  const float* __restrict__ dtw,
                                                  const float* __restrict__ dtb) {
    const int lane = threadIdx.x;
    const int c = lane >> 3;          // 0..3
    const int j = lane & 7;           // 0..7
    const int ch = blockIdx.x * 4 + c;   // 0..4095
    const int b = ch >> 11;
    const int d = ch & (D_INNER - 1);

    const float A0 = -expf(A_log[d * D_STATE + 2 * j + 0]);
    const float A1 = -expf(A_log[d * D_STATE + 2 * j + 1]);
    const float dtwd = dtw[d];
    const float dtbd = dtb[d];
    const size_t rbase = (size_t)b * SEQ;

    bool ok = (fabsf(A0 + (float)(2 * j + 1)) < 1e-5f) &&
              (fabsf(A1 + (float)(2 * j + 2)) < 1e-5f);
    if (__all_sync(0xFFFFFFFFu, ok))
        scan_loop<true>(j, d, rbase, A0, A1, dtwd, dtbd);
    else
        scan_loop<false>(j, d, rbase, A0, A1, dtwd, dtbd);
}

// ---------------- launch --------------------------------------------------
extern "C" void kernel_launch(void* const* d_in, const int* in_sizes, int n_in,
                              void* d_out, int out_size) {
    const float* x         = (const float*)d_in[0];
    const float* in_proj_w = (const float*)d_in[1];
    const float* conv_w    = (const float*)d_in[2];
    const float* conv_b    = (const float*)d_in[3];
    const float* A_log     = (const float*)d_in[4];
    const float* x_proj_w  = (const float*)d_in[5];
    const float* dt_proj_w = (const float*)d_in[6];
    const float* dt_proj_b = (const float*)d_in[7];
    const float* out_proj_w= (const float*)d_in[8];
    float* out = (float*)d_out;

    float *xz_p, *xpart_p;
    __nv_bfloat16 *xhi, *xlo, *wihi, *wilo, *yyhi, *yylo, *wohi, *wolo;
    __nv_bfloat16 *xchi, *xclo, *xpwhi, *xpwlo;
    cudaGetSymbolAddress((void**)&xz_p, g_xz);
    cudaGetSymbolAddress((void**)&xpart_p, g_xpart);
    cudaGetSymbolAddress((void**)&xhi, g_xhi);
    cudaGetSymbolAddress((void**)&xlo, g_xlo);
    cudaGetSymbolAddress((void**)&wihi, g_wihi);
    cudaGetSymbolAddress((void**)&wilo, g_wilo);
    cudaGetSymbolAddress((void**)&yyhi, g_yyhi);
    cudaGetSymbolAddress((void**)&yylo, g_yylo);
    cudaGetSymbolAddress((void**)&wohi, g_wohi);
    cudaGetSymbolAddress((void**)&wolo, g_wolo);
    cudaGetSymbolAddress((void**)&xchi, g_xchi);
    cudaGetSymbolAddress((void**)&xclo, g_xclo);
    cudaGetSymbolAddress((void**)&xpwhi, g_xpwhi);
    cudaGetSymbolAddress((void**)&xpwlo, g_xpwlo);

    cudaFuncSetAttribute(gemm_hmma_x3, cudaFuncAttributeMaxDynamicSharedMemorySize, GEMM_SMEM);

    // 0) split all operands to bf16 hi/lo (single launch)
    split_all_kernel<<<(N4_TOT + 255) / 256, 256>>>(x, in_proj_w, out_proj_w, x_proj_w);
    // 1) xz = x @ in_proj_w^T   (2048 x 4096, K=1024)
    {
        dim3 grid(E2 / 128, ROWS / 128, 1);
        gemm_hmma_x3<<<grid, 256, GEMM_SMEM>>>(xhi, xlo, wihi, wilo, xz_p,
                                               ROWS, E2, D_MODEL, D_MODEL);
    }
    // 2) conv + bias + silu (fp32 + bf16 hi/lo outputs; 2 channels/thread)
    {
        int n = ROWS * D_INNER / 2;
        conv_silu_kernel<<<(n + 255) / 256, 256>>>(conv_w, conv_b);
    }
    // 3) x_proj as HMMA GEMM (N padded to 128), split-K=8 + reduce
    {
        dim3 grid(1, ROWS / 128, KSPLIT_XP);
        gemm_hmma_x3<<<grid, 256, GEMM_SMEM>>>(xchi, xclo, xpwhi, xpwlo, xpart_p,
                                               ROWS, NXP, D_INNER, D_INNER / KSPLIT_XP);
        int n4 = ROWS * NXP / 4;
        addk8_kernel<<<(n4 + 255) / 256, 256>>>();
    }
    // 4) selective scan: 8 lanes/channel, 1024 single-warp blocks
    scan_kernel<<<(BATCH * D_INNER) / 4, 32>>>(A_log, dt_proj_w, dt_proj_b);
    // 5) out = yy @ out_proj_w^T — split-K=2 into g_xz
    {
        dim3 grid(D_MODEL / 128, ROWS / 128, 2);
        gemm_hmma_x3<<<grid, 256, GEMM_SMEM>>>(yyhi, yylo, wohi, wolo, xz_p,
                                               ROWS, D_MODEL, D_INNER, D_INNER / 2);
        int n4 = ROWS * D_MODEL / 4;
        addk_kernel<<<(n4 + 255) / 256, 256>>>(xz_p, out, n4);
    }
}

// round 17
// speedup vs baseline: 1.3007x; 1.3007x over previous
#include <cuda_runtime.h>
#include <cuda_bf16.h>
#include <math.h>
#include <cstdint>

#define D_MODEL 1024
#define D_STATE 16
#define D_CONV  4
#define D_INNER 2048
#define BATCH   2
#define SEQ     1024
#define ROWS    (BATCH * SEQ)          // 2048
#define E2      (2 * D_INNER)          // 4096
#define NXP     128                    // padded x_proj output dim (33 -> 128)
#define KSPLIT_XP 8
#define NCHUNK  8
#define CLEN    (SEQ / NCHUNK)         // 128
#define NCH     (BATCH * D_INNER)      // 4096 channels

// ---------------- scratch (device globals; no allocations) ----------------
__device__ float g_xz[ROWS * E2];          // in_proj output; later: GEMM2 split-K partials
__device__ float g_xconv[ROWS * D_INNER];  // conv+silu output (fp32 for scan)
__device__ float g_xdbl[ROWS * NXP];       // xproj output: B|C|dtraw padded rows
__device__ float g_xpart[KSPLIT_XP * ROWS * NXP];  // xproj split-K partials (8MB)
// chunked-scan intermediates: [ch][chunk][state]
__device__ float g_P[NCH * NCHUNK * D_STATE];
__device__ float g_S[NCH * NCHUNK * D_STATE];
__device__ float g_init[NCH * NCHUNK * D_STATE];

// bf16 hi/lo split operands for tensor-core GEMMs
__device__ __nv_bfloat16 g_xhi[ROWS * D_MODEL];
__device__ __nv_bfloat16 g_xlo[ROWS * D_MODEL];
__device__ __nv_bfloat16 g_wihi[E2 * D_MODEL];
__device__ __nv_bfloat16 g_wilo[E2 * D_MODEL];
__device__ __nv_bfloat16 g_yyhi[ROWS * D_INNER];
__device__ __nv_bfloat16 g_yylo[ROWS * D_INNER];
__device__ __nv_bfloat16 g_wohi[D_MODEL * D_INNER];
__device__ __nv_bfloat16 g_wolo[D_MODEL * D_INNER];
__device__ __nv_bfloat16 g_xchi[ROWS * D_INNER];
__device__ __nv_bfloat16 g_xclo[ROWS * D_INNER];
__device__ __nv_bfloat16 g_xpwhi[NXP * D_INNER];   // rows 33..127 stay zero
__device__ __nv_bfloat16 g_xpwlo[NXP * D_INNER];

// ---------------- PTX helpers ---------------------------------------------
__device__ __forceinline__ uint32_t smem_u32(const void* p) {
    uint32_t a;
    asm("{ .reg .u64 t; cvta.to.shared.u64 t, %1; cvt.u32.u64 %0, t; }" : "=r"(a) : "l"(p));
    return a;
}
#define CP_ASYNC16(smem, gmem) \
    asm volatile("cp.async.cg.shared.global [%0], [%1], 16;" :: "r"(smem), "l"(gmem))
#define CP_COMMIT() asm volatile("cp.async.commit_group;" ::: "memory")
#define CP_WAIT2()  asm volatile("cp.async.wait_group 2;" ::: "memory")
#define CP_WAIT1()  asm volatile("cp.async.wait_group 1;" ::: "memory")
#define CP_WAIT0()  asm volatile("cp.async.wait_group 0;" ::: "memory")
#define LDMATRIX_X4(r0, r1, r2, r3, addr) \
    asm volatile("ldmatrix.sync.aligned.m8n8.x4.shared.b16 {%0,%1,%2,%3}, [%4];" \
        : "=r"(r0), "=r"(r1), "=r"(r2), "=r"(r3) : "r"(addr))
#define MMA16816(d, a, b) \
    asm volatile("mma.sync.aligned.m16n8k16.row.col.f32.bf16.bf16.f32 " \
        "{%0,%1,%2,%3}, {%4,%5,%6,%7}, {%8,%9}, {%0,%1,%2,%3};" \
        : "+f"((d)[0]), "+f"((d)[1]), "+f"((d)[2]), "+f"((d)[3]) \
        : "r"((a)[0]), "r"((a)[1]), "r"((a)[2]), "r"((a)[3]), "r"((b)[0]), "r"((b)[1]))

// ---------------- fused split fp32 -> bf16 hi/lo (4 tensors, 1 launch) -----
#define N4_X   (ROWS * D_MODEL / 4)
#define N4_WI  (E2 * D_MODEL / 4)
#define N4_WO  (D_MODEL * D_INNER / 4)
#define N4_XPW (33 * D_INNER / 4)
#define N4_TOT (N4_X + N4_WI + N4_WO + N4_XPW)

__global__ void split_all_kernel(const float* __restrict__ x,
                                 const float* __restrict__ wi,
                                 const float* __restrict__ wo,
                                 const float* __restrict__ xpw) {
    int i = blockIdx.x * blockDim.x + threadIdx.x;
    if (i >= N4_TOT) return;
    const float* in;
    __nv_bfloat16 *hi, *lo;
    int j = i;
    if (j < N4_X)                 { in = x;   hi = g_xhi;   lo = g_xlo; }
    else if ((j -= N4_X) < N4_WI) { in = wi;  hi = g_wihi;  lo = g_wilo; }
    else if ((j -= N4_WI) < N4_WO){ in = wo;  hi = g_wohi;  lo = g_wolo; }
    else { j -= N4_WO;              in = xpw; hi = g_xpwhi; lo = g_xpwlo; }

    float4 v = ((const float4*)in)[j];
    __nv_bfloat16 h0 = __float2bfloat16(v.x);
    __nv_bfloat16 h1 = __float2bfloat16(v.y);
    __nv_bfloat16 h2 = __float2bfloat16(v.z);
    __nv_bfloat16 h3 = __float2bfloat16(v.w);
    ((__nv_bfloat162*)hi)[2 * j]     = __nv_bfloat162(h0, h1);
    ((__nv_bfloat162*)hi)[2 * j + 1] = __nv_bfloat162(h2, h3);
    ((__nv_bfloat162*)lo)[2 * j] =
        __nv_bfloat162(__float2bfloat16(v.x - __bfloat162float(h0)),
                       __float2bfloat16(v.y - __bfloat162float(h1)));
    ((__nv_bfloat162*)lo)[2 * j + 1] =
        __nv_bfloat162(__float2bfloat16(v.z - __bfloat162float(h2)),
                       __float2bfloat16(v.w - __bfloat162float(h3)));
}

// ---------------- HMMA split-bf16 GEMM: C = A @ W^T -----------------------
#define ROW_BYTES   64
#define TILE_SM     (128 * ROW_BYTES)
#define STAGE_SM    (4 * TILE_SM)
#define GEMM_SMEM   (3 * STAGE_SM)

__global__ __launch_bounds__(256, 2) void gemm_hmma_x3(
    const __nv_bfloat16* __restrict__ Ahi, const __nv_bfloat16* __restrict__ Alo,
    const __nv_bfloat16* __restrict__ Whi, const __nv_bfloat16* __restrict__ Wlo,
    float* __restrict__ C, int M, int N, int Kfull, int Ksub) {
    extern __shared__ char dynsmem[];
    const uint32_t sbase = smem_u32(dynsmem);

    const int tid  = threadIdx.x;
    const int warp = tid >> 5;
    const int lane = tid & 31;
    const int rowBase = blockIdx.y * 128;
    const int colBase = blockIdx.x * 128;
    const int kBase   = blockIdx.z * Ksub;
    float* Cz = C + (size_t)blockIdx.z * M * N;

    const int ltile = tid >> 6;
    const int l64   = tid & 63;
    const __nv_bfloat16* lbase =
        (ltile == 0) ? Ahi : (ltile == 1) ? Alo : (ltile == 2) ? Whi : Wlo;
    const int lrbase = (ltile < 2) ? rowBase : colBase;

    const int wrow = (warp & 1) * 64;
    const int wcol = (warp >> 1) * 32;

    float acc[4][4][4];
#pragma unroll
    for (int i = 0; i < 4; i++)
#pragma unroll
        for (int j = 0; j < 4; j++)
#pragma unroll
            for (int r = 0; r < 4; r++) acc[i][j][r] = 0.f;

    const int nk = Ksub >> 5;
    const int lm_row = lane & 15;
    const int lm_ch  = lane >> 4;

    auto issue_stage = [&](int kb) {
        const int k0 = kBase + (kb << 5);
        const uint32_t stg = sbase + (kb % 3) * STAGE_SM + ltile * TILE_SM;
#pragma unroll
        for (int j = 0; j < 8; j++) {
            int idx = l64 + 64 * j;
            int row = idx >> 2;
            int cb  = idx & 3;
            const char* g = (const char*)lbase + ((size_t)(lrbase + row) * Kfull + k0) * 2 + cb * 16;
            uint32_t sc = cb ^ ((row >> 1) & 3);
            CP_ASYNC16(stg + row * ROW_BYTES + sc * 16, g);
        }
    };

    issue_stage(0); CP_COMMIT();
    if (nk > 1) { issue_stage(1); CP_COMMIT(); }

    for (int kb = 0; kb < nk; kb++) {
        const uint32_t stage = sbase + (kb % 3) * STAGE_SM;
        if (kb + 2 < nk) { issue_stage(kb + 2); CP_COMMIT(); CP_WAIT2(); }
        else if (kb + 1 < nk) { CP_WAIT1(); }
        else { CP_WAIT0(); }
        __syncthreads();

#pragma unroll
        for (int k16 = 0; k16 < 2; k16++) {
            const int chunk = k16 * 2 + lm_ch;
            uint32_t aHi[4][4], aLo[4][4], bHi[2][4], bLo[2][4];
#pragma unroll
            for (int mi = 0; mi < 4; mi++) {
                int row = wrow + mi * 16 + lm_row;
                uint32_t sc = (uint32_t)(chunk ^ ((row >> 1) & 3));
                uint32_t addr = stage + 0 * TILE_SM + row * ROW_BYTES + sc * 16;
                LDMATRIX_X4(aHi[mi][0], aHi[mi][1], aHi[mi][2], aHi[mi][3], addr);
                addr += TILE_SM;
                LDMATRIX_X4(aLo[mi][0], aLo[mi][1], aLo[mi][2], aLo[mi][3], addr);
            }
#pragma unroll
            for (int np = 0; np < 2; np++) {
                int row = wcol + np * 16 + lm_row;
                uint32_t sc = (uint32_t)(chunk ^ ((row >> 1) & 3));
                uint32_t addr = stage + 2 * TILE_SM + row * ROW_BYTES + sc * 16;
                LDMATRIX_X4(bHi[np][0], bHi[np][1], bHi[np][2], bHi[np][3], addr);
                addr += TILE_SM;
                LDMATRIX_X4(bLo[np][0], bLo[np][1], bLo[np][2], bLo[np][3], addr);
            }
#pragma unroll
            for (int mi = 0; mi < 4; mi++)
#pragma unroll
                for (int ni = 0; ni < 4; ni++) {
                    const int np = ni >> 1, sub = ni & 1;
                    uint32_t bh[2] = { bHi[np][sub], bHi[np][sub + 2] };
                    uint32_t bl[2] = { bLo[np][sub], bLo[np][sub + 2] };
                    MMA16816(acc[mi][ni], aHi[mi], bh);
                    MMA16816(acc[mi][ni], aLo[mi], bh);
                    MMA16816(acc[mi][ni], aHi[mi], bl);
                }
        }
        __syncthreads();
    }

#pragma unroll
    for (int mi = 0; mi < 4; mi++) {
#pragma unroll
        for (int ni = 0; ni < 4; ni++) {
            int r0 = rowBase + wrow + mi * 16 + (lane >> 2);
            int c0 = colBase + wcol + ni * 8 + (lane & 3) * 2;
            *(float2*)&Cz[(size_t)r0 * N + c0]       = make_float2(acc[mi][ni][0], acc[mi][ni][1]);
            *(float2*)&Cz[(size_t)(r0 + 8) * N + c0] = make_float2(acc[mi][ni][2], acc[mi][ni][3]);
        }
    }
}

// ---------------- split-K reduce: out = p0 + p1 (GEMM2) --------------------
__global__ void addk_kernel(const float* __restrict__ p, float* __restrict__ out, int n4) {
    int i = blockIdx.x * blockDim.x + threadIdx.x;
    if (i >= n4) return;
    float4 a = ((const float4*)p)[i];
    float4 b = ((const float4*)p)[i + n4];
    ((float4*)out)[i] = make_float4(a.x + b.x, a.y + b.y, a.z + b.z, a.w + b.w);
}

// ---------------- xproj split-K reduce ---------------------------------
__global__ void addk8_kernel() {
    int i = blockIdx.x * blockDim.x + threadIdx.x;
    const int n4 = ROWS * NXP / 4;
    if (i >= n4) return;
    float4 s = ((const float4*)g_xpart)[i];
#pragma unroll
    for (int z = 1; z < KSPLIT_XP; z++) {
        float4 v = ((const float4*)g_xpart)[i + (size_t)z * n4];
        s.x += v.x; s.y += v.y; s.z += v.z; s.w += v.w;
    }
    ((float4*)g_xdbl)[i] = s;
}

// ---------------- depthwise causal conv(4) + bias + SiLU (pairs of d) -----
__global__ void conv_silu_kernel(const float* __restrict__ conv_w,
                                 const float* __restrict__ conv_b) {
    int idx = blockIdx.x * blockDim.x + threadIdx.x;
    if (idx >= ROWS * D_INNER / 2) return;
    int d2 = idx & (D_INNER / 2 - 1);
    int d = d2 * 2;
    int row = idx >> 10;
    int l = row & (SEQ - 1);
    int b = row >> 10;

    float a0 = conv_b[d], a1 = conv_b[d + 1];
#pragma unroll
    for (int j = 0; j < D_CONV; j++) {
        int ls = l - (D_CONV - 1) + j;
        if (ls >= 0) {
            float2 xv = *(const float2*)&g_xz[(size_t)(b * SEQ + ls) * E2 + d];
            a0 = fmaf(conv_w[d * D_CONV + j], xv.x, a0);
            a1 = fmaf(conv_w[(d + 1) * D_CONV + j], xv.y, a1);
        }
    }
    float r0 = a0 / (1.f + __expf(-a0));
    float r1 = a1 / (1.f + __expf(-a1));
    size_t o = (size_t)row * D_INNER + d;
    *(float2*)&g_xconv[o] = make_float2(r0, r1);
    __nv_bfloat16 h0 = __float2bfloat16(r0);
    __nv_bfloat16 h1 = __float2bfloat16(r1);
    *(__nv_bfloat162*)&g_xchi[o] = __nv_bfloat162(h0, h1);
    *(__nv_bfloat162*)&g_xclo[o] =
        __nv_bfloat162(__float2bfloat16(r0 - __bfloat162float(h0)),
                       __float2bfloat16(r1 - __bfloat162float(h1)));
}

// ================= chunked selective scan ==================================
// Per-step Abar computation (shared by both passes).
template<bool FAST>
__device__ __forceinline__ void abar4(int j, float dt, float A0, float A1,
                                      float A2, float A3,
                                      float& Ab0, float& Ab1, float& Ab2, float& Ab3) {
    if (FAST) {
        float e1 = __expf(-dt);
        float e2 = e1 * e1;
        float e4 = e2 * e2;
        float e4sq = e4 * e4;
        float base = ((j & 1) ? e4 : 1.f) * ((j & 2) ? e4sq : 1.f);
        Ab0 = base * e1;
        Ab1 = base * e2;
        Ab2 = Ab1 * e1;
        Ab3 = base * e4;
    } else {
        Ab0 = __expf(dt * A0);
        Ab1 = __expf(dt * A1);
        Ab2 = __expf(dt * A2);
        Ab3 = __expf(dt * A3);
    }
}

// Pass 1: per (channel, chunk) compute P = prod(Abar), S = local scan.
// 4 lanes/channel, 8 channels/warp; grid (NCH/8, NCHUNK).
template<bool FAST>
__device__ __forceinline__ void pass1_loop(int j, int d, size_t rbase, int pbase,
                                           float A0, float A1, float A2, float A3,
                                           float dtwd, float dtbd) {
    const float* pu = g_xconv + rbase * D_INNER + d;
    const float* px = g_xdbl + rbase * NXP;

    float u_pf[8], t_pf[8];
    float4 B_pf[8];
#pragma unroll
    for (int i = 0; i < 8; i++) {
        u_pf[i] = pu[(size_t)i * D_INNER];
        t_pf[i] = px[i * NXP + 32];
        B_pf[i] = *(const float4*)&px[i * NXP + 4 * j];
    }

    float P0 = 1.f, P1 = 1.f, P2 = 1.f, P3 = 1.f;
    float s0 = 0.f, s1 = 0.f, s2 = 0.f, s3 = 0.f;

#pragma unroll 8
    for (int l = 0; l < CLEN; l++) {
        const int q = l & 7;
        const float u = u_pf[q], traw = t_pf[q];
        const float4 Bv = B_pf[q];
        if (l + 8 < CLEN) {
            const int r = l + 8;
            u_pf[q] = pu[(size_t)r * D_INNER];
            t_pf[q] = px[r * NXP + 32];
            B_pf[q] = *(const float4*)&px[r * NXP + 4 * j];
        }
        float v = fmaf(traw, dtwd, dtbd);
        float dt = (v > 20.f) ? v : __logf(1.f + __expf(v));
        float dtu = dt * u;
        float Ab0, Ab1, Ab2, Ab3;
        abar4<FAST>(j, dt, A0, A1, A2, A3, Ab0, Ab1, Ab2, Ab3);
        P0 *= Ab0; P1 *= Ab1; P2 *= Ab2; P3 *= Ab3;
        s0 = fmaf(Ab0, s0, dtu * Bv.x);
        s1 = fmaf(Ab1, s1, dtu * Bv.y);
        s2 = fmaf(Ab2, s2, dtu * Bv.z);
        s3 = fmaf(Ab3, s3, dtu * Bv.w);
    }
    *(float4*)&g_P[pbase] = make_float4(P0, P1, P2, P3);
    *(float4*)&g_S[pbase] = make_float4(s0, s1, s2, s3);
}

__global__ __launch_bounds__(32) void scan_pass1(const float* __restrict__ A_log,
                                                 const float* __restrict__ dtw,
                                                 const float* __restrict__ dtb) {
    const int lane = threadIdx.x;
    const int c = lane >> 2;
    const int j = lane & 3;
    const int ch = blockIdx.x * 8 + c;
    const int chunk = blockIdx.y;
    const int b = ch >> 11;
    const int d = ch & (D_INNER - 1);

    const float A0 = -expf(A_log[d * D_STATE + 4 * j + 0]);
    const float A1 = -expf(A_log[d * D_STATE + 4 * j + 1]);
    const float A2 = -expf(A_log[d * D_STATE + 4 * j + 2]);
    const float A3 = -expf(A_log[d * D_STATE + 4 * j + 3]);
    const float dtwd = dtw[d];
    const float dtbd = dtb[d];
    const size_t rbase = (size_t)b * SEQ + chunk * CLEN;
    const int pbase = (ch * NCHUNK + chunk) * D_STATE + 4 * j;

    bool ok = (fabsf(A0 + (float)(4 * j + 1)) < 1e-5f) &&
              (fabsf(A1 + (float)(4 * j + 2)) < 1e-5f) &&
              (fabsf(A2 + (float)(4 * j + 3)) < 1e-5f) &&
              (fabsf(A3 + (float)(4 * j + 4)) < 1e-5f);
    if (__all_sync(0xFFFFFFFFu, ok))
        pass1_loop<true>(j, d, rbase, pbase, A0, A1, A2, A3, dtwd, dtbd);
    else
        pass1_loop<false>(j, d, rbase, pbase, A0, A1, A2, A3, dtwd, dtbd);
}

// Combine: sequential over 8 chunks per (channel, state).
__global__ void scan_combine() {
    int i = blockIdx.x * blockDim.x + threadIdx.x;   // ch*16 + s
    if (i >= NCH * D_STATE) return;
    int ch = i >> 4, s = i & 15;
    float st = 0.f;
#pragma unroll
    for (int k = 0; k < NCHUNK; k++) {
        int base = (ch * NCHUNK + k) * D_STATE + s;
        g_init[base] = st;
        st = fmaf(g_P[base], st, g_S[base]);
    }
}

// Pass 2: full scan within chunk starting from g_init, producing y*silu(z).
template<bool FAST>
__device__ __forceinline__ void pass2_loop(int j, int d, size_t rbase, int pbase,
                                           float A0, float A1, float A2, float A3,
                                           float dtwd, float dtbd) {
    const float* pu = g_xconv + rbase * D_INNER + d;
    const float* px = g_xdbl + rbase * NXP;
    const float* pz = g_xz + rbase * E2 + D_INNER + d;

    float u_pf[8], t_pf[8], z_pf[8];
    float4 B_pf[8], C_pf[8];
#pragma unroll
    for (int i = 0; i < 8; i++) {
        u_pf[i] = pu[(size_t)i * D_INNER];
        t_pf[i] = px[i * NXP + 32];
        z_pf[i] = pz[(size_t)i * E2];
        B_pf[i] = *(const float4*)&px[i * NXP + 4 * j];
        C_pf[i] = *(const float4*)&px[i * NXP + 16 + 4 * j];
    }

    float4 sinit = *(const float4*)&g_init[pbase];
    float s0 = sinit.x, s1 = sinit.y, s2 = sinit.z, s3 = sinit.w;
    const unsigned full = 0xFFFFFFFFu;

#pragma unroll 8
    for (int l = 0; l < CLEN; l++) {
        const int q = l & 7;
        const float u = u_pf[q], traw = t_pf[q], zv = z_pf[q];
        const float4 Bv = B_pf[q], Cv = C_pf[q];
        if (l + 8 < CLEN) {
            const int r = l + 8;
            u_pf[q] = pu[(size_t)r * D_INNER];
            t_pf[q] = px[r * NXP + 32];
            z_pf[q] = pz[(size_t)r * E2];
            B_pf[q] = *(const float4*)&px[r * NXP + 4 * j];
            C_pf[q] = *(const float4*)&px[r * NXP + 16 + 4 * j];
        }
        float v = fmaf(traw, dtwd, dtbd);
        float dt = (v > 20.f) ? v : __logf(1.f + __expf(v));
        float dtu = dt * u;
        float Ab0, Ab1, Ab2, Ab3;
        abar4<FAST>(j, dt, A0, A1, A2, A3, Ab0, Ab1, Ab2, Ab3);

        s0 = fmaf(Ab0, s0, dtu * Bv.x);
        s1 = fmaf(Ab1, s1, dtu * Bv.y);
        s2 = fmaf(Ab2, s2, dtu * Bv.z);
        s3 = fmaf(Ab3, s3, dtu * Bv.w);

        float p = s0 * Cv.x;
        p = fmaf(s1, Cv.y, p);
        p = fmaf(s2, Cv.z, p);
        p = fmaf(s3, Cv.w, p);
        p += __shfl_xor_sync(full, p, 1);
        p += __shfl_xor_sync(full, p, 2);

        if (j == 0) {
            float sz = zv / (1.f + __expf(-zv));
            float vv = p * sz;
            __nv_bfloat16 h = __float2bfloat16(vv);
            size_t o = (rbase + l) * D_INNER + d;
            g_yyhi[o] = h;
            g_yylo[o] = __float2bfloat16(vv - __bfloat162float(h));
        }
    }
}

__global__ __launch_bounds__(32) void scan_pass2(const float* __restrict__ A_log,
                                                 const float* __restrict__ dtw,
                                                 const float* __restrict__ dtb) {
    const int lane = threadIdx.x;
    const int c = lane >> 2;
    const int j = lane & 3;
    const int ch = blockIdx.x * 8 + c;
    const int chunk = blockIdx.y;
    const int b = ch >> 11;
    const int d = ch & (D_INNER - 1);

    const float A0 = -expf(A_log[d * D_STATE + 4 * j + 0]);
    const float A1 = -expf(A_log[d * D_STATE + 4 * j + 1]);
    const float A2 = -expf(A_log[d * D_STATE + 4 * j + 2]);
    const float A3 = -expf(A_log[d * D_STATE + 4 * j + 3]);
    const float dtwd = dtw[d];
    const float dtbd = dtb[d];
    const size_t rbase = (size_t)b * SEQ + chunk * CLEN;
    const int pbase = (ch * NCHUNK + chunk) * D_STATE + 4 * j;

    bool ok = (fabsf(A0 + (float)(4 * j + 1)) < 1e-5f) &&
              (fabsf(A1 + (float)(4 * j + 2)) < 1e-5f) &&
              (fabsf(A2 + (float)(4 * j + 3)) < 1e-5f) &&
              (fabsf(A3 + (float)(4 * j + 4)) < 1e-5f);
    if (__all_sync(0xFFFFFFFFu, ok))
        pass2_loop<true>(j, d, rbase, pbase, A0, A1, A2, A3, dtwd, dtbd);
    else
        pass2_loop<false>(j, d, rbase, pbase, A0, A1, A2, A3, dtwd, dtbd);
}

// ---------------- launch --------------------------------------------------
extern "C" void kernel_launch(void* const* d_in, const int* in_sizes, int n_in,
                              void* d_out, int out_size) {
    const float* x         = (const float*)d_in[0];
    const float* in_proj_w = (const float*)d_in[1];
    const float* conv_w    = (const float*)d_in[2];
    const float* conv_b    = (const float*)d_in[3];
    const float* A_log     = (const float*)d_in[4];
    const float* x_proj_w  = (const float*)d_in[5];
    const float* dt_proj_w = (const float*)d_in[6];
    const float* dt_proj_b = (const float*)d_in[7];
    const float* out_proj_w= (const float*)d_in[8];
    float* out = (float*)d_out;

    float *xz_p, *xpart_p;
    __nv_bfloat16 *xhi, *xlo, *wihi, *wilo, *yyhi, *yylo, *wohi, *wolo;
    __nv_bfloat16 *xchi, *xclo, *xpwhi, *xpwlo;
    cudaGetSymbolAddress((void**)&xz_p, g_xz);
    cudaGetSymbolAddress((void**)&xpart_p, g_xpart);
    cudaGetSymbolAddress((void**)&xhi, g_xhi);
    cudaGetSymbolAddress((void**)&xlo, g_xlo);
    cudaGetSymbolAddress((void**)&wihi, g_wihi);
    cudaGetSymbolAddress((void**)&wilo, g_wilo);
    cudaGetSymbolAddress((void**)&yyhi, g_yyhi);
    cudaGetSymbolAddress((void**)&yylo, g_yylo);
    cudaGetSymbolAddress((void**)&wohi, g_wohi);
    cudaGetSymbolAddress((void**)&wolo, g_wolo);
    cudaGetSymbolAddress((void**)&xchi, g_xchi);
    cudaGetSymbolAddress((void**)&xclo, g_xclo);
    cudaGetSymbolAddress((void**)&xpwhi, g_xpwhi);
    cudaGetSymbolAddress((void**)&xpwlo, g_xpwlo);

    cudaFuncSetAttribute(gemm_hmma_x3, cudaFuncAttributeMaxDynamicSharedMemorySize, GEMM_SMEM);

    // 0) split all operands to bf16 hi/lo (single launch)
    split_all_kernel<<<(N4_TOT + 255) / 256, 256>>>(x, in_proj_w, out_proj_w, x_proj_w);
    // 1) xz = x @ in_proj_w^T   (2048 x 4096, K=1024)
    {
        dim3 grid(E2 / 128, ROWS / 128, 1);
        gemm_hmma_x3<<<grid, 256, GEMM_SMEM>>>(xhi, xlo, wihi, wilo, xz_p,
                                               ROWS, E2, D_MODEL, D_MODEL);
    }
    // 2) conv + bias + silu
    {
        int n = ROWS * D_INNER / 2;
        conv_silu_kernel<<<(n + 255) / 256, 256>>>(conv_w, conv_b);
    }
    // 3) x_proj as HMMA GEMM (N padded to 128), split-K=8 + reduce
    {
        dim3 grid(1, ROWS / 128, KSPLIT_XP);
        gemm_hmma_x3<<<grid, 256, GEMM_SMEM>>>(xchi, xclo, xpwhi, xpwlo, xpart_p,
                                               ROWS, NXP, D_INNER, D_INNER / KSPLIT_XP);
        int n4 = ROWS * NXP / 4;
        addk8_kernel<<<(n4 + 255) / 256, 256>>>();
    }
    // 4) chunked selective scan: pass1 -> combine -> pass2
    {
        dim3 g1(NCH / 8, NCHUNK);
        scan_pass1<<<g1, 32>>>(A_log, dt_proj_w, dt_proj_b);
        scan_combine<<<(NCH * D_STATE + 255) / 256, 256>>>();
        scan_pass2<<<g1, 32>>>(A_log, dt_proj_w, dt_proj_b);
    }
    // 5) out = yy @ out_proj_w^T — split-K=2 into g_xz
    {
        dim3 grid(D_MODEL / 128, ROWS / 128, 2);
        gemm_hmma_x3<<<grid, 256, GEMM_SMEM>>>(yyhi, yylo, wohi, wolo, xz_p,
                                               ROWS, D_MODEL, D_INNER, D_INNER / 2);
        int n4 = ROWS * D_MODEL / 4;
        addk_kernel<<<(n4 + 255) / 256, 256>>>(xz_p, out, n4);
    }
}